// round 13
// baseline (speedup 1.0000x reference)
#include <cuda_runtime.h>

// DempsterSchaferCombine — converged kernel, final A/B: store policy.
//
// Algebraic collapse: the reference's per-pixel Dirichlet/DS combine
//   S=sum(a), b=(a-1)/S, u=C/S, K, denom=1-K, b_a, u_a, S_a, out=b_a*S_a+1
// cancels exactly (denom, S1, S2 all drop out) to the pure elementwise form
//   out = (a1-1)*(a2-1)/21 + a1 + a2 - 1            (rel_err ~8e-8)
// => minimal traffic: 352 MB read + 176 MB write.
//
// Converged config (12 rounds): one-shot grid, 128-thr CTAs,
// __launch_bounds__(128,16), one 256-bit v8 chunk per thread per array,
// ld.global.nc.v8 loads, 32-bit indexing, branch-free exact tiling
// (44,040,192 = 43008 blocks * 1024 floats). ~69.7us kernel, DRAM 86.8%.
// R13 change: stores default write-back (st.global.v8) instead of .cs —
// the one untested cell in the A/B matrix.

#define INV_C (1.0f / 21.0f)

__device__ __forceinline__ void ld256_nc(const float* p, float v[8]) {
    asm volatile(
        "ld.global.nc.v8.f32 {%0,%1,%2,%3,%4,%5,%6,%7}, [%8];"
        : "=f"(v[0]), "=f"(v[1]), "=f"(v[2]), "=f"(v[3]),
          "=f"(v[4]), "=f"(v[5]), "=f"(v[6]), "=f"(v[7])
        : "l"(p));
}

__device__ __forceinline__ void st256_wb(float* p, const float v[8]) {
    asm volatile(
        "st.global.v8.f32 [%0], {%1,%2,%3,%4,%5,%6,%7,%8};"
        :: "l"(p),
           "f"(v[0]), "f"(v[1]), "f"(v[2]), "f"(v[3]),
           "f"(v[4]), "f"(v[5]), "f"(v[6]), "f"(v[7])
        : "memory");
}

// Exact path: one 8-float chunk per thread, no predicates, 32-bit indexing.
// Requires n % (128*8) == 0, n < 2^31, 32B-aligned pointers.
__global__ __launch_bounds__(128, 16) void ds_combine_v8_wb(
    const float* __restrict__ a1,
    const float* __restrict__ a2,
    float* __restrict__ out)
{
    unsigned int base = (blockIdx.x * 128u + threadIdx.x) * 8u;

    float x[8], y[8], r[8];
    ld256_nc(a1 + base, x);
    ld256_nc(a2 + base, y);

#pragma unroll
    for (int k = 0; k < 8; k++)
        r[k] = fmaf((x[k] - 1.0f) * (y[k] - 1.0f), INV_C, x[k] + y[k] - 1.0f);

    st256_wb(out + base, r);
}

__device__ __forceinline__ float4 ds4(float4 x, float4 y) {
    float4 r;
    r.x = fmaf((x.x - 1.0f) * (y.x - 1.0f), INV_C, x.x + y.x - 1.0f);
    r.y = fmaf((x.y - 1.0f) * (y.y - 1.0f), INV_C, x.y + y.y - 1.0f);
    r.z = fmaf((x.z - 1.0f) * (y.z - 1.0f), INV_C, x.z + y.z - 1.0f);
    r.w = fmaf((x.w - 1.0f) * (y.w - 1.0f), INV_C, x.w + y.w - 1.0f);
    return r;
}

// Guarded fallback (float4) for shapes not divisible by 1024 floats/block.
__global__ __launch_bounds__(256, 8) void ds_combine_guarded(
    const float4* __restrict__ a1,
    const float4* __restrict__ a2,
    float4* __restrict__ out,
    int n4)
{
    int i0 = blockIdx.x * 512 + threadIdx.x;
    int i1 = i0 + 256;
    if (i1 < n4) {
        float4 x0 = __ldcs(a1 + i0);
        float4 x1 = __ldcs(a1 + i1);
        float4 y0 = __ldcs(a2 + i0);
        float4 y1 = __ldcs(a2 + i1);
        __stcs(out + i0, ds4(x0, y0));
        __stcs(out + i1, ds4(x1, y1));
    } else if (i0 < n4) {
        float4 x0 = __ldcs(a1 + i0);
        float4 y0 = __ldcs(a2 + i0);
        __stcs(out + i0, ds4(x0, y0));
    }
}

// Scalar tail for n % 4 != 0 (not hit for this shape; kept for safety).
__global__ void ds_combine_tail(
    const float* __restrict__ a1,
    const float* __restrict__ a2,
    float* __restrict__ out,
    int start, int n)
{
    int i = start + blockIdx.x * blockDim.x + threadIdx.x;
    if (i >= n) return;
    float x = a1[i], y = a2[i];
    out[i] = fmaf((x - 1.0f) * (y - 1.0f), INV_C, x + y - 1.0f);
}

extern "C" void kernel_launch(void* const* d_in, const int* in_sizes, int n_in,
                              void* d_out, int out_size)
{
    const float* a1 = (const float*)d_in[0];
    const float* a2 = (const float*)d_in[1];
    float* out = (float*)d_out;

    int n = out_size;                    // 8*21*512*512 = 44,040,192
    const int floats_per_block = 128 * 8;  // 1024

    if (n % floats_per_block == 0) {
        // This shape: 43008 blocks of 128 threads, branch-free, 256-bit ld/st.
        ds_combine_v8_wb<<<n / floats_per_block, 128>>>(a1, a2, out);
    } else {
        int n4 = n >> 2;
        int blocks = (n4 + 511) / 512;
        ds_combine_guarded<<<blocks, 256>>>(
            (const float4*)a1, (const float4*)a2, (float4*)out, n4);
        int tail_start = n4 << 2;
        if (n - tail_start > 0)
            ds_combine_tail<<<1, 128>>>(a1, a2, out, tail_start, n);
    }
}